// round 16
// baseline (speedup 1.0000x reference)
#include <cuda_runtime.h>
#include <cuda_bf16.h>
#include <cuda_fp16.h>
#include <math.h>

#define NN    100000
#define EE    1600000
#define HH    4
#define DD    128
#define BM    64
#define BK    16

// ---------------- scratch (device globals) ----------------
__device__ unsigned g_xf[NN * 64];     // x as packed fp16x2 [N][64]
__device__ unsigned g_hf[NN * 64];     // h as packed fp16x2 [N][64]
__device__ unsigned g_skipf[NN * 64];  // skip as packed fp16x2 [N][64]
__device__ unsigned g_Wf[64 * 256];    // [W | skip_W] fp16, packed k-pairs [64 kp][256 n]
__device__ float    g_as[NN * HH];
__device__ float    g_ad[NN * HH];
__device__ int      g_cnt[NN];
__device__ int      g_exc[NN];
__device__ int      g_bsum[128];
__device__ int      g_boff[128];
__device__ int      g_off[NN + 1];
__device__ int      g_cur[NN];
__device__ int      g_esrc[EE];
__device__ int      g_is64;

// ---------------- helpers ----------------
__device__ __forceinline__ float lrelu(float v) { return v > 0.0f ? v : 0.2f * v; }

__device__ __forceinline__ void mma_fp16(float4& c, const unsigned a[4],
                                         unsigned b0, unsigned b1) {
    asm volatile(
        "mma.sync.aligned.m16n8k16.row.col.f32.f16.f16.f32 "
        "{%0,%1,%2,%3}, {%4,%5,%6,%7}, {%8,%9}, {%0,%1,%2,%3};"
        : "+f"(c.x), "+f"(c.y), "+f"(c.z), "+f"(c.w)
        : "r"(a[0]), "r"(a[1]), "r"(a[2]), "r"(a[3]), "r"(b0), "r"(b1));
}

__device__ __forceinline__ void ldsm_x4(unsigned r[4], const unsigned* smem_ptr) {
    unsigned addr = (unsigned)__cvta_generic_to_shared(smem_ptr);
    asm volatile("ldmatrix.sync.aligned.m8n8.x4.shared.b16 {%0,%1,%2,%3}, [%4];"
                 : "=r"(r[0]), "=r"(r[1]), "=r"(r[2]), "=r"(r[3]) : "r"(addr));
}

__device__ __forceinline__ unsigned pack_h2(float a, float b) {
    __half2 r = __floats2half2_rn(a, b);
    return *(unsigned*)&r;
}

__device__ __forceinline__ void cp16(unsigned* dst_smem, const unsigned* src) {
    unsigned d = (unsigned)__cvta_generic_to_shared(dst_smem);
    asm volatile("cp.async.cg.shared.global [%0], [%1], 16;" :: "r"(d), "l"(src));
}

__device__ __forceinline__ float4 unpack4(uint2 w) {
    float2 f0 = __half22float2(*(__half2*)&w.x);
    float2 f1 = __half22float2(*(__half2*)&w.y);
    return make_float4(f0.x, f0.y, f1.x, f1.y);
}

// ---------------- kernels ----------------
__global__ void detect_k(const long long* ei) {
    if (blockIdx.x == 0 && threadIdx.x == 0) {
        int ok64 = 1;
        for (int i = 0; i < 64; i++) {
            long long v = ei[i];
            if (v < 0 || v >= NN) { ok64 = 0; break; }
        }
        g_is64 = ok64;
    }
}

// combined prep: blocks [0,64): pack W|skip_W; blocks [64, ...): pack x
__global__ void prep_k(const float* __restrict__ W, const float* __restrict__ sW,
                       const float* __restrict__ x) {
    if (blockIdx.x < 64) {
        int i = blockIdx.x * 256 + threadIdx.x;
        int kp = i >> 8, c = i & 255;
        float v0, v1;
        if (c < 128) { v0 = W[(2 * kp) * 128 + c];        v1 = W[(2 * kp + 1) * 128 + c]; }
        else         { v0 = sW[(2 * kp) * 128 + c - 128]; v1 = sW[(2 * kp + 1) * 128 + c - 128]; }
        g_Wf[i] = pack_h2(v0, v1);
    } else {
        int i = (blockIdx.x - 64) * 256 + threadIdx.x;
        if (i < NN * 32) {
            float4 v = ((const float4*)x)[i];
            ((uint2*)g_xf)[i] = make_uint2(pack_h2(v.x, v.y), pack_h2(v.z, v.w));
        }
    }
}

__global__ void init_k() {
    int i = blockIdx.x * blockDim.x + threadIdx.x;
    if (i < NN) g_cnt[i] = 0;
}

// 2 edges per thread, vectorized dst loads
__global__ void hist_k(const void* __restrict__ ei) {
    int i = (blockIdx.x * blockDim.x + threadIdx.x) * 2;
    if (i >= EE) return;
    if (g_is64) {
        longlong2 v = *(const longlong2*)((const long long*)ei + EE + i);
        atomicAdd(&g_cnt[(int)v.x], 1);
        atomicAdd(&g_cnt[(int)v.y], 1);
    } else {
        int2 v = *(const int2*)((const int*)ei + EE + i);
        atomicAdd(&g_cnt[v.x], 1);
        atomicAdd(&g_cnt[v.y], 1);
    }
}

__global__ void __launch_bounds__(1024) scanA_k() {
    __shared__ int sd[1024];
    int t = threadIdx.x;
    int i = blockIdx.x * 1024 + t;
    int v = (i < NN) ? g_cnt[i] : 0;
    sd[t] = v;
    __syncthreads();
#pragma unroll
    for (int o = 1; o < 1024; o <<= 1) {
        int x = (t >= o) ? sd[t - o] : 0;
        __syncthreads();
        sd[t] += x;
        __syncthreads();
    }
    if (i < NN) g_exc[i] = sd[t] - v;
    if (t == 1023) g_bsum[blockIdx.x] = sd[t];
}

__global__ void scanB_k(int nblocks) {
    __shared__ int sd[128];
    int t = threadIdx.x;
    int v = (t < nblocks) ? g_bsum[t] : 0;
    sd[t] = v;
    __syncthreads();
#pragma unroll
    for (int o = 1; o < 128; o <<= 1) {
        int x = (t >= o) ? sd[t - o] : 0;
        __syncthreads();
        sd[t] += x;
        __syncthreads();
    }
    g_boff[t] = sd[t] - v;
}

__global__ void scanC_k() {
    int i = blockIdx.x * blockDim.x + threadIdx.x;
    if (i < NN) {
        int off = g_exc[i] + g_boff[i >> 10];
        g_off[i] = off;
        g_cur[i] = off;
    }
    if (i == 0) g_off[NN] = EE;
}

// scatter a sub-range [e0, e1) of edges; 2 edges per thread
__global__ void scatter_k(const void* __restrict__ ei, int e0, int e1) {
    int i = e0 + (blockIdx.x * blockDim.x + threadIdx.x) * 2;
    if (i >= e1) return;
    int s0, d0, s1, d1;
    if (g_is64) {
        const long long* p = (const long long*)ei;
        longlong2 sv = *(const longlong2*)(p + i);
        longlong2 dv = *(const longlong2*)(p + EE + i);
        s0 = (int)sv.x; s1 = (int)sv.y; d0 = (int)dv.x; d1 = (int)dv.y;
    } else {
        const int* p = (const int*)ei;
        int2 sv = *(const int2*)(p + i);
        int2 dv = *(const int2*)(p + EE + i);
        s0 = sv.x; s1 = sv.y; d0 = dv.x; d1 = dv.y;
    }
    g_esrc[atomicAdd(&g_cur[d0], 1)] = s0;
    if (i + 1 < e1) g_esrc[atomicAdd(&g_cur[d1], 1)] = s1;
}

// fp16 GEMM: tile M=64, N=128 per block; A and W staged purely via cp.async.
// A-fragments via ldmatrix.x4.
// blockIdx.y = 0: h-half -> g_hf + fused att logits; 1: skip-half -> g_skipf
#define XP 12    // A smem pitch in u32
#define WP 136   // B smem pitch in u32
__global__ void __launch_bounds__(256, 4) gemm_fp16_k(const float* __restrict__ asrc,
                                                      const float* __restrict__ adst) {
    __shared__ __align__(16) unsigned xs[2][BM * XP];
    __shared__ __align__(16) unsigned ws[2][8 * WP];
    int t = threadIdx.x;
    int wid = t >> 5, lane = t & 31;
    int gid = lane >> 2, tig = lane & 3;
    int wm = wid >> 2, wn = wid & 3;
    int m0 = blockIdx.x * BM;
    int half = blockIdx.y;
    int ncol0 = half * 128;

    int wr  = t >> 5;
    int wc4 = (t & 31) * 4;
    int arow = t >> 1;
    int ach  = (t & 1) * 4;
    bool astage = t < 128;
    int arow_g = m0 + arow; if (arow_g >= NN) arow_g = NN - 1;
    const unsigned* abase = g_xf + (size_t)arow_g * 64 + ach;

    float4 acc[2][4];
#pragma unroll
    for (int mi = 0; mi < 2; mi++)
#pragma unroll
        for (int j = 0; j < 4; j++) acc[mi][j] = make_float4(0.f, 0.f, 0.f, 0.f);

    // ---- prologue ----
    {
        cp16(&ws[0][wr * WP + wc4], &g_Wf[wr * 256 + ncol0 + wc4]);
        if (astage) cp16(&xs[0][arow * XP + ach], abase);
        asm volatile("cp.async.commit_group;");
        asm volatile("cp.async.wait_group 0;");
        __syncthreads();
    }

    for (int it = 0; it < 8; it++) {
        int cur = it & 1, nxt = cur ^ 1;
        bool more = (it < 7);
        if (more) {
            int kp0 = (it + 1) * 8;
            cp16(&ws[nxt][wr * WP + wc4], &g_Wf[(kp0 + wr) * 256 + ncol0 + wc4]);
            if (astage) cp16(&xs[nxt][arow * XP + ach], abase + kp0);
            asm volatile("cp.async.commit_group;");
        }

        unsigned ah[2][4];
#pragma unroll
        for (int mi = 0; mi < 2; mi++) {
            int rb0 = wm * 32 + mi * 16;
            ldsm_x4(ah[mi], &xs[cur][(rb0 + (lane & 15)) * XP + (lane >> 4) * 4]);
        }
#pragma unroll
        for (int j = 0; j < 4; j++) {
            int col = wn * 32 + j * 8 + gid;
            unsigned b0 = ws[cur][tig * WP + col];
            unsigned b1 = ws[cur][(tig + 4) * WP + col];
            mma_fp16(acc[0][j], ah[0], b0, b1);
            mma_fp16(acc[1][j], ah[1], b0, b1);
        }

        if (more) {
            asm volatile("cp.async.wait_group 0;");
            __syncthreads();
        }
    }

    if (half == 0) {
#pragma unroll
        for (int mi = 0; mi < 2; mi++) {
            int row  = m0 + wm * 32 + mi * 16 + gid;
            int row2 = row + 8;
            float ps0 = 0.f, pd0 = 0.f, ps1 = 0.f, pd1 = 0.f;
#pragma unroll
            for (int j = 0; j < 4; j++) {
                int col = wn * 32 + j * 8 + tig * 2;
                if (row  < NN) g_hf[(size_t)row  * 64 + (col >> 1)] =
                    pack_h2(acc[mi][j].x, acc[mi][j].y);
                if (row2 < NN) g_hf[(size_t)row2 * 64 + (col >> 1)] =
                    pack_h2(acc[mi][j].z, acc[mi][j].w);
                float as0 = asrc[col], as1 = asrc[col + 1];
                float ad0 = adst[col], ad1 = adst[col + 1];
                ps0 += acc[mi][j].x * as0 + acc[mi][j].y * as1;
                pd0 += acc[mi][j].x * ad0 + acc[mi][j].y * ad1;
                ps1 += acc[mi][j].z * as0 + acc[mi][j].w * as1;
                pd1 += acc[mi][j].z * ad0 + acc[mi][j].w * ad1;
            }
#pragma unroll
            for (int o = 1; o <= 2; o <<= 1) {
                ps0 += __shfl_xor_sync(0xffffffff, ps0, o);
                pd0 += __shfl_xor_sync(0xffffffff, pd0, o);
                ps1 += __shfl_xor_sync(0xffffffff, ps1, o);
                pd1 += __shfl_xor_sync(0xffffffff, pd1, o);
            }
            if (tig == 0) {
                if (row < NN)  { g_as[row * 4 + wn]  = ps0; g_ad[row * 4 + wn]  = pd0; }
                if (row2 < NN) { g_as[row2 * 4 + wn] = ps1; g_ad[row2 * 4 + wn] = pd1; }
            }
        }
    } else {
#pragma unroll
        for (int mi = 0; mi < 2; mi++) {
#pragma unroll
            for (int j = 0; j < 4; j++) {
                int col  = wn * 32 + j * 8 + tig * 2;
                int row  = m0 + wm * 32 + mi * 16 + gid;
                int row2 = row + 8;
                if (row  < NN) g_skipf[(size_t)row  * 64 + (col >> 1)] =
                    pack_h2(acc[mi][j].x, acc[mi][j].y);
                if (row2 < NN) g_skipf[(size_t)row2 * 64 + (col >> 1)] =
                    pack_h2(acc[mi][j].z, acc[mi][j].w);
            }
        }
    }
}

// Fused CSR aggregation + softmax-norm + bias + skip + LayerNorm (warp/node)
// fully predicated 8-wide batches: MLP=cnt on every iteration, no serial tail
__global__ void __launch_bounds__(256) eagg_k(const float* __restrict__ gb,
                                              const float* __restrict__ sb,
                                              const float* __restrict__ lg,
                                              const float* __restrict__ lb,
                                              float* __restrict__ out) {
    int g = blockIdx.x * blockDim.x + threadIdx.x;
    int n = g >> 5, lane = g & 31;
    if (n >= NN) return;
    int h = lane >> 3;

    float ad_h = g_ad[n * 4 + h];

    // self loop
    float p = __expf(lrelu(g_as[n * 4 + h] + ad_h));
    float4 hv = unpack4(((const uint2*)(g_hf + (size_t)n * 64))[lane]);
    float z = p;
    float4 acc = make_float4(p * hv.x, p * hv.y, p * hv.z, p * hv.w);

    int e   = g_off[n];
    int end = g_off[n + 1];
    while (e < end) {
        int cnt = end - e;              // warp-uniform
        int s[8]; float a[8]; uint2 w[8];
#pragma unroll
        for (int q = 0; q < 8; q++) { s[q] = 0; a[q] = 0.f; w[q] = make_uint2(0u, 0u); }
#pragma unroll
        for (int q = 0; q < 8; q++) if (q < cnt) s[q] = __ldg(g_esrc + e + q);
#pragma unroll
        for (int q = 0; q < 8; q++) if (q < cnt) a[q] = __ldg(g_as + s[q] * 4 + h);
#pragma unroll
        for (int q = 0; q < 8; q++) if (q < cnt)
            w[q] = ((const uint2*)(g_hf + (size_t)s[q] * 64))[lane];
#pragma unroll
        for (int q = 0; q < 8; q++) {
            float pq = (q < cnt) ? __expf(lrelu(a[q] + ad_h)) : 0.f;
            z += pq;
            float4 hq = unpack4(w[q]);
            acc.x += pq * hq.x; acc.y += pq * hq.y;
            acc.z += pq * hq.z; acc.w += pq * hq.w;
        }
        e += 8;
    }

    float inv = 1.0f / (z + 1e-16f);
    float4 sk = unpack4(((const uint2*)(g_skipf + (size_t)n * 64))[lane]);
    float4 b1 = ((const float4*)gb)[lane];
    float4 b2 = ((const float4*)sb)[lane];
    float4 v;
    v.x = acc.x * inv + sk.x + b1.x + b2.x;
    v.y = acc.y * inv + sk.y + b1.y + b2.y;
    v.z = acc.z * inv + sk.z + b1.z + b2.z;
    v.w = acc.w * inv + sk.w + b1.w + b2.w;

    float sum = v.x + v.y + v.z + v.w;
    float sq  = v.x * v.x + v.y * v.y + v.z * v.z + v.w * v.w;
#pragma unroll
    for (int o = 16; o >= 1; o >>= 1) {
        sum += __shfl_xor_sync(0xffffffff, sum, o);
        sq  += __shfl_xor_sync(0xffffffff, sq, o);
    }
    float mu  = sum * (1.0f / 128.0f);
    float var = sq * (1.0f / 128.0f) - mu * mu;
    float invs = rsqrtf(var + 1e-5f);
    float4 gg = ((const float4*)lg)[lane];
    float4 bb = ((const float4*)lb)[lane];
    float4 o4;
    o4.x = (v.x - mu) * invs * gg.x + bb.x;
    o4.y = (v.y - mu) * invs * gg.y + bb.y;
    o4.z = (v.z - mu) * invs * gg.z + bb.z;
    o4.w = (v.w - mu) * invs * gg.w + bb.w;
    ((float4*)(out + (size_t)n * 128))[lane] = o4;
}

// ---------------- stream setup (lazy, first kernel_launch call) ----------------
struct Streams {
    cudaStream_t s1 = 0;
    cudaEvent_t  ev0 = 0, ev1 = 0, ev2 = 0;
    bool ok = false;
    Streams() {
        ok = cudaStreamCreateWithFlags(&s1, cudaStreamNonBlocking) == cudaSuccess &&
             cudaEventCreateWithFlags(&ev0, cudaEventDisableTiming) == cudaSuccess &&
             cudaEventCreateWithFlags(&ev1, cudaEventDisableTiming) == cudaSuccess &&
             cudaEventCreateWithFlags(&ev2, cudaEventDisableTiming) == cudaSuccess;
    }
};

// ---------------- launch ----------------
extern "C" void kernel_launch(void* const* d_in, const int* in_sizes, int n_in,
                              void* d_out, int out_size) {
    const float* x        = (const float*)d_in[0];
    const void*  ei       = d_in[1];
    const float* W        = (const float*)d_in[2];
    const float* att_src  = (const float*)d_in[3];
    const float* att_dst  = (const float*)d_in[4];
    const float* gat_bias = (const float*)d_in[5];
    const float* skip_W   = (const float*)d_in[6];
    const float* skip_b   = (const float*)d_in[7];
    const float* ln_g     = (const float*)d_in[8];
    const float* ln_b     = (const float*)d_in[9];
    float* out = (float*)d_out;

    int nblocks = (NN + 1023) / 1024;
    dim3 ggrid((NN + BM - 1) / BM, 2);
    int prep_blocks = 64 + (NN * 32 + 255) / 256;
    const int EHALF = EE / 2;
    int sc_blocks = (EHALF / 2 + 255) / 256;

    static Streams st;

    if (st.ok) {
        detect_k<<<1, 32>>>((const long long*)ei);
        cudaEventRecord(st.ev0, 0);
        cudaStreamWaitEvent(st.s1, st.ev0, 0);
        // side stream: CSR build
        init_k<<<(NN + 255) / 256, 256, 0, st.s1>>>();
        hist_k<<<(EE / 2 + 255) / 256, 256, 0, st.s1>>>(ei);
        scanA_k<<<nblocks, 1024, 0, st.s1>>>();
        scanB_k<<<1, 128, 0, st.s1>>>(nblocks);
        scanC_k<<<(NN + 255) / 256, 256, 0, st.s1>>>();
        cudaEventRecord(st.ev2, st.s1);
        scatter_k<<<sc_blocks, 256, 0, st.s1>>>(ei, 0, EHALF);
        cudaEventRecord(st.ev1, st.s1);
        // main stream: prep + GEMM
        prep_k<<<prep_blocks, 256>>>(W, skip_W, x);
        gemm_fp16_k<<<ggrid, 256>>>(att_src, att_dst);
        cudaStreamWaitEvent(0, st.ev2, 0);
        scatter_k<<<sc_blocks, 256>>>(ei, EHALF, EE);
        cudaStreamWaitEvent(0, st.ev1, 0);
        eagg_k<<<(NN * 32 + 255) / 256, 256>>>(gat_bias, skip_b, ln_g, ln_b, out);
    } else {
        detect_k<<<1, 32>>>((const long long*)ei);
        prep_k<<<prep_blocks, 256>>>(W, skip_W, x);
        init_k<<<(NN + 255) / 256, 256>>>();
        gemm_fp16_k<<<ggrid, 256>>>(att_src, att_dst);
        hist_k<<<(EE / 2 + 255) / 256, 256>>>(ei);
        scanA_k<<<nblocks, 1024>>>();
        scanB_k<<<1, 128>>>(nblocks);
        scanC_k<<<(NN + 255) / 256, 256>>>();
        scatter_k<<<(EE / 2 + 255) / 256, 256>>>(ei, 0, EE);
        eagg_k<<<(NN * 32 + 255) / 256, 256>>>(gat_bias, skip_b, ln_g, ln_b, out);
    }
}

// round 17
// speedup vs baseline: 1.1764x; 1.1764x over previous
#include <cuda_runtime.h>
#include <cuda_bf16.h>
#include <cuda_fp16.h>
#include <math.h>

#define NN    100000
#define EE    1600000
#define HH    4
#define DD    128
#define BM    64
#define BK    16

// ---------------- scratch (device globals) ----------------
__device__ unsigned g_xf[NN * 64];     // x as packed fp16x2 [N][64]
__device__ unsigned g_hf[NN * 64];     // h as packed fp16x2 [N][64]
__device__ unsigned g_skipf[NN * 64];  // skip as packed fp16x2 [N][64]
__device__ unsigned g_Wf[64 * 256];    // [W | skip_W] fp16, packed k-pairs [64 kp][256 n]
__device__ float    g_as[NN * HH];
__device__ float    g_ad[NN * HH];
__device__ int      g_cnt[NN];
__device__ int      g_exc[NN];
__device__ int      g_bsum[128];
__device__ int      g_boff[128];
__device__ int      g_off[NN + 1];
__device__ int      g_cur[NN];
__device__ int      g_esrc[EE];
__device__ int      g_is64;

// ---------------- helpers ----------------
__device__ __forceinline__ float lrelu(float v) { return v > 0.0f ? v : 0.2f * v; }

__device__ __forceinline__ void mma_fp16(float4& c, const unsigned a[4],
                                         unsigned b0, unsigned b1) {
    asm volatile(
        "mma.sync.aligned.m16n8k16.row.col.f32.f16.f16.f32 "
        "{%0,%1,%2,%3}, {%4,%5,%6,%7}, {%8,%9}, {%0,%1,%2,%3};"
        : "+f"(c.x), "+f"(c.y), "+f"(c.z), "+f"(c.w)
        : "r"(a[0]), "r"(a[1]), "r"(a[2]), "r"(a[3]), "r"(b0), "r"(b1));
}

__device__ __forceinline__ void ldsm_x4(unsigned r[4], const unsigned* smem_ptr) {
    unsigned addr = (unsigned)__cvta_generic_to_shared(smem_ptr);
    asm volatile("ldmatrix.sync.aligned.m8n8.x4.shared.b16 {%0,%1,%2,%3}, [%4];"
                 : "=r"(r[0]), "=r"(r[1]), "=r"(r[2]), "=r"(r[3]) : "r"(addr));
}

__device__ __forceinline__ unsigned pack_h2(float a, float b) {
    __half2 r = __floats2half2_rn(a, b);
    return *(unsigned*)&r;
}

__device__ __forceinline__ void cp16(unsigned* dst_smem, const unsigned* src) {
    unsigned d = (unsigned)__cvta_generic_to_shared(dst_smem);
    asm volatile("cp.async.cg.shared.global [%0], [%1], 16;" :: "r"(d), "l"(src));
}

__device__ __forceinline__ float4 unpack4(uint2 w) {
    float2 f0 = __half22float2(*(__half2*)&w.x);
    float2 f1 = __half22float2(*(__half2*)&w.y);
    return make_float4(f0.x, f0.y, f1.x, f1.y);
}

// ---------------- kernels ----------------
__global__ void detect_k(const long long* ei) {
    if (blockIdx.x == 0 && threadIdx.x == 0) {
        int ok64 = 1;
        for (int i = 0; i < 64; i++) {
            long long v = ei[i];
            if (v < 0 || v >= NN) { ok64 = 0; break; }
        }
        g_is64 = ok64;
    }
}

// combined prep: blocks [0,64): pack W|skip_W; blocks [64, ...): pack x
__global__ void prep_k(const float* __restrict__ W, const float* __restrict__ sW,
                       const float* __restrict__ x) {
    if (blockIdx.x < 64) {
        int i = blockIdx.x * 256 + threadIdx.x;
        int kp = i >> 8, c = i & 255;
        float v0, v1;
        if (c < 128) { v0 = W[(2 * kp) * 128 + c];        v1 = W[(2 * kp + 1) * 128 + c]; }
        else         { v0 = sW[(2 * kp) * 128 + c - 128]; v1 = sW[(2 * kp + 1) * 128 + c - 128]; }
        g_Wf[i] = pack_h2(v0, v1);
    } else {
        int i = (blockIdx.x - 64) * 256 + threadIdx.x;
        if (i < NN * 32) {
            float4 v = ((const float4*)x)[i];
            ((uint2*)g_xf)[i] = make_uint2(pack_h2(v.x, v.y), pack_h2(v.z, v.w));
        }
    }
}

__global__ void init_k() {
    int i = blockIdx.x * blockDim.x + threadIdx.x;
    if (i < NN) g_cnt[i] = 0;
}

// 2 edges per thread, vectorized dst loads
__global__ void hist_k(const void* __restrict__ ei) {
    int i = (blockIdx.x * blockDim.x + threadIdx.x) * 2;
    if (i >= EE) return;
    if (g_is64) {
        longlong2 v = *(const longlong2*)((const long long*)ei + EE + i);
        atomicAdd(&g_cnt[(int)v.x], 1);
        atomicAdd(&g_cnt[(int)v.y], 1);
    } else {
        int2 v = *(const int2*)((const int*)ei + EE + i);
        atomicAdd(&g_cnt[v.x], 1);
        atomicAdd(&g_cnt[v.y], 1);
    }
}

__global__ void __launch_bounds__(1024) scanA_k() {
    __shared__ int sd[1024];
    int t = threadIdx.x;
    int i = blockIdx.x * 1024 + t;
    int v = (i < NN) ? g_cnt[i] : 0;
    sd[t] = v;
    __syncthreads();
#pragma unroll
    for (int o = 1; o < 1024; o <<= 1) {
        int x = (t >= o) ? sd[t - o] : 0;
        __syncthreads();
        sd[t] += x;
        __syncthreads();
    }
    if (i < NN) g_exc[i] = sd[t] - v;
    if (t == 1023) g_bsum[blockIdx.x] = sd[t];
}

__global__ void scanB_k(int nblocks) {
    __shared__ int sd[128];
    int t = threadIdx.x;
    int v = (t < nblocks) ? g_bsum[t] : 0;
    sd[t] = v;
    __syncthreads();
#pragma unroll
    for (int o = 1; o < 128; o <<= 1) {
        int x = (t >= o) ? sd[t - o] : 0;
        __syncthreads();
        sd[t] += x;
        __syncthreads();
    }
    g_boff[t] = sd[t] - v;
}

__global__ void scanC_k() {
    int i = blockIdx.x * blockDim.x + threadIdx.x;
    if (i < NN) {
        int off = g_exc[i] + g_boff[i >> 10];
        g_off[i] = off;
        g_cur[i] = off;
    }
    if (i == 0) g_off[NN] = EE;
}

// scatter a sub-range [e0, e1) of edges; 2 edges per thread
__global__ void scatter_k(const void* __restrict__ ei, int e0, int e1) {
    int i = e0 + (blockIdx.x * blockDim.x + threadIdx.x) * 2;
    if (i >= e1) return;
    int s0, d0, s1, d1;
    if (g_is64) {
        const long long* p = (const long long*)ei;
        longlong2 sv = *(const longlong2*)(p + i);
        longlong2 dv = *(const longlong2*)(p + EE + i);
        s0 = (int)sv.x; s1 = (int)sv.y; d0 = (int)dv.x; d1 = (int)dv.y;
    } else {
        const int* p = (const int*)ei;
        int2 sv = *(const int2*)(p + i);
        int2 dv = *(const int2*)(p + EE + i);
        s0 = sv.x; s1 = sv.y; d0 = dv.x; d1 = dv.y;
    }
    g_esrc[atomicAdd(&g_cur[d0], 1)] = s0;
    if (i + 1 < e1) g_esrc[atomicAdd(&g_cur[d1], 1)] = s1;
}

// fp16 GEMM: tile M=64, N=128 per block; A and W staged purely via cp.async.
// A-fragments via ldmatrix.x4.
// blockIdx.y = 0: h-half -> g_hf + fused att logits; 1: skip-half -> g_skipf
#define XP 12    // A smem pitch in u32
#define WP 136   // B smem pitch in u32
__global__ void __launch_bounds__(256, 4) gemm_fp16_k(const float* __restrict__ asrc,
                                                      const float* __restrict__ adst) {
    __shared__ __align__(16) unsigned xs[2][BM * XP];
    __shared__ __align__(16) unsigned ws[2][8 * WP];
    int t = threadIdx.x;
    int wid = t >> 5, lane = t & 31;
    int gid = lane >> 2, tig = lane & 3;
    int wm = wid >> 2, wn = wid & 3;
    int m0 = blockIdx.x * BM;
    int half = blockIdx.y;
    int ncol0 = half * 128;

    int wr  = t >> 5;
    int wc4 = (t & 31) * 4;
    int arow = t >> 1;
    int ach  = (t & 1) * 4;
    bool astage = t < 128;
    int arow_g = m0 + arow; if (arow_g >= NN) arow_g = NN - 1;
    const unsigned* abase = g_xf + (size_t)arow_g * 64 + ach;

    float4 acc[2][4];
#pragma unroll
    for (int mi = 0; mi < 2; mi++)
#pragma unroll
        for (int j = 0; j < 4; j++) acc[mi][j] = make_float4(0.f, 0.f, 0.f, 0.f);

    // ---- prologue ----
    {
        cp16(&ws[0][wr * WP + wc4], &g_Wf[wr * 256 + ncol0 + wc4]);
        if (astage) cp16(&xs[0][arow * XP + ach], abase);
        asm volatile("cp.async.commit_group;");
        asm volatile("cp.async.wait_group 0;");
        __syncthreads();
    }

    for (int it = 0; it < 8; it++) {
        int cur = it & 1, nxt = cur ^ 1;
        bool more = (it < 7);
        if (more) {
            int kp0 = (it + 1) * 8;
            cp16(&ws[nxt][wr * WP + wc4], &g_Wf[(kp0 + wr) * 256 + ncol0 + wc4]);
            if (astage) cp16(&xs[nxt][arow * XP + ach], abase + kp0);
            asm volatile("cp.async.commit_group;");
        }

        unsigned ah[2][4];
#pragma unroll
        for (int mi = 0; mi < 2; mi++) {
            int rb0 = wm * 32 + mi * 16;
            ldsm_x4(ah[mi], &xs[cur][(rb0 + (lane & 15)) * XP + (lane >> 4) * 4]);
        }
#pragma unroll
        for (int j = 0; j < 4; j++) {
            int col = wn * 32 + j * 8 + gid;
            unsigned b0 = ws[cur][tig * WP + col];
            unsigned b1 = ws[cur][(tig + 4) * WP + col];
            mma_fp16(acc[0][j], ah[0], b0, b1);
            mma_fp16(acc[1][j], ah[1], b0, b1);
        }

        if (more) {
            asm volatile("cp.async.wait_group 0;");
            __syncthreads();
        }
    }

    if (half == 0) {
#pragma unroll
        for (int mi = 0; mi < 2; mi++) {
            int row  = m0 + wm * 32 + mi * 16 + gid;
            int row2 = row + 8;
            float ps0 = 0.f, pd0 = 0.f, ps1 = 0.f, pd1 = 0.f;
#pragma unroll
            for (int j = 0; j < 4; j++) {
                int col = wn * 32 + j * 8 + tig * 2;
                if (row  < NN) g_hf[(size_t)row  * 64 + (col >> 1)] =
                    pack_h2(acc[mi][j].x, acc[mi][j].y);
                if (row2 < NN) g_hf[(size_t)row2 * 64 + (col >> 1)] =
                    pack_h2(acc[mi][j].z, acc[mi][j].w);
                float as0 = asrc[col], as1 = asrc[col + 1];
                float ad0 = adst[col], ad1 = adst[col + 1];
                ps0 += acc[mi][j].x * as0 + acc[mi][j].y * as1;
                pd0 += acc[mi][j].x * ad0 + acc[mi][j].y * ad1;
                ps1 += acc[mi][j].z * as0 + acc[mi][j].w * as1;
                pd1 += acc[mi][j].z * ad0 + acc[mi][j].w * ad1;
            }
#pragma unroll
            for (int o = 1; o <= 2; o <<= 1) {
                ps0 += __shfl_xor_sync(0xffffffff, ps0, o);
                pd0 += __shfl_xor_sync(0xffffffff, pd0, o);
                ps1 += __shfl_xor_sync(0xffffffff, ps1, o);
                pd1 += __shfl_xor_sync(0xffffffff, pd1, o);
            }
            if (tig == 0) {
                if (row < NN)  { g_as[row * 4 + wn]  = ps0; g_ad[row * 4 + wn]  = pd0; }
                if (row2 < NN) { g_as[row2 * 4 + wn] = ps1; g_ad[row2 * 4 + wn] = pd1; }
            }
        }
    } else {
#pragma unroll
        for (int mi = 0; mi < 2; mi++) {
#pragma unroll
            for (int j = 0; j < 4; j++) {
                int col  = wn * 32 + j * 8 + tig * 2;
                int row  = m0 + wm * 32 + mi * 16 + gid;
                int row2 = row + 8;
                if (row  < NN) g_skipf[(size_t)row  * 64 + (col >> 1)] =
                    pack_h2(acc[mi][j].x, acc[mi][j].y);
                if (row2 < NN) g_skipf[(size_t)row2 * 64 + (col >> 1)] =
                    pack_h2(acc[mi][j].z, acc[mi][j].w);
            }
        }
    }
}

// Fused CSR aggregation + softmax-norm + bias + skip + LayerNorm (warp/node)
// 8-wide unguarded batches + 4-wide batch stage + short serial tail.
__global__ void __launch_bounds__(256) eagg_k(const float* __restrict__ gb,
                                              const float* __restrict__ sb,
                                              const float* __restrict__ lg,
                                              const float* __restrict__ lb,
                                              float* __restrict__ out) {
    int g = blockIdx.x * blockDim.x + threadIdx.x;
    int n = g >> 5, lane = g & 31;
    if (n >= NN) return;
    int h = lane >> 3;

    float ad_h = g_ad[n * 4 + h];

    // self loop
    float p = __expf(lrelu(g_as[n * 4 + h] + ad_h));
    float4 hv = unpack4(((const uint2*)(g_hf + (size_t)n * 64))[lane]);
    float z = p;
    float4 acc = make_float4(p * hv.x, p * hv.y, p * hv.z, p * hv.w);

    int e   = g_off[n];
    int end = g_off[n + 1];
    for (; e + 8 <= end; e += 8) {
        int s[8];
#pragma unroll
        for (int q = 0; q < 8; q++) s[q] = __ldg(g_esrc + e + q);
        float a[8];
#pragma unroll
        for (int q = 0; q < 8; q++) a[q] = __ldg(g_as + s[q] * 4 + h);
        uint2 w[8];
#pragma unroll
        for (int q = 0; q < 8; q++) w[q] = ((const uint2*)(g_hf + (size_t)s[q] * 64))[lane];
#pragma unroll
        for (int q = 0; q < 8; q++) {
            float pq = __expf(lrelu(a[q] + ad_h));
            z += pq;
            float4 hq = unpack4(w[q]);
            acc.x += pq * hq.x; acc.y += pq * hq.y;
            acc.z += pq * hq.z; acc.w += pq * hq.w;
        }
    }
    if (e + 4 <= end) {
        int s[4];
#pragma unroll
        for (int q = 0; q < 4; q++) s[q] = __ldg(g_esrc + e + q);
        float a[4];
#pragma unroll
        for (int q = 0; q < 4; q++) a[q] = __ldg(g_as + s[q] * 4 + h);
        uint2 w[4];
#pragma unroll
        for (int q = 0; q < 4; q++) w[q] = ((const uint2*)(g_hf + (size_t)s[q] * 64))[lane];
#pragma unroll
        for (int q = 0; q < 4; q++) {
            float pq = __expf(lrelu(a[q] + ad_h));
            z += pq;
            float4 hq = unpack4(w[q]);
            acc.x += pq * hq.x; acc.y += pq * hq.y;
            acc.z += pq * hq.z; acc.w += pq * hq.w;
        }
        e += 4;
    }
    for (; e < end; e++) {
        int s0 = __ldg(g_esrc + e);
        float a0 = __ldg(g_as + s0 * 4 + h);
        float4 h0 = unpack4(((const uint2*)(g_hf + (size_t)s0 * 64))[lane]);
        float p0 = __expf(lrelu(a0 + ad_h));
        z += p0;
        acc.x += p0 * h0.x; acc.y += p0 * h0.y;
        acc.z += p0 * h0.z; acc.w += p0 * h0.w;
    }

    float inv = 1.0f / (z + 1e-16f);
    float4 sk = unpack4(((const uint2*)(g_skipf + (size_t)n * 64))[lane]);
    float4 b1 = ((const float4*)gb)[lane];
    float4 b2 = ((const float4*)sb)[lane];
    float4 v;
    v.x = acc.x * inv + sk.x + b1.x + b2.x;
    v.y = acc.y * inv + sk.y + b1.y + b2.y;
    v.z = acc.z * inv + sk.z + b1.z + b2.z;
    v.w = acc.w * inv + sk.w + b1.w + b2.w;

    float sum = v.x + v.y + v.z + v.w;
    float sq  = v.x * v.x + v.y * v.y + v.z * v.z + v.w * v.w;
#pragma unroll
    for (int o = 16; o >= 1; o >>= 1) {
        sum += __shfl_xor_sync(0xffffffff, sum, o);
        sq  += __shfl_xor_sync(0xffffffff, sq, o);
    }
    float mu  = sum * (1.0f / 128.0f);
    float var = sq * (1.0f / 128.0f) - mu * mu;
    float invs = rsqrtf(var + 1e-5f);
    float4 gg = ((const float4*)lg)[lane];
    float4 bb = ((const float4*)lb)[lane];
    float4 o4;
    o4.x = (v.x - mu) * invs * gg.x + bb.x;
    o4.y = (v.y - mu) * invs * gg.y + bb.y;
    o4.z = (v.z - mu) * invs * gg.z + bb.z;
    o4.w = (v.w - mu) * invs * gg.w + bb.w;
    ((float4*)(out + (size_t)n * 128))[lane] = o4;
}

// ---------------- stream setup (lazy, first kernel_launch call) ----------------
struct Streams {
    cudaStream_t s1 = 0;
    cudaEvent_t  ev0 = 0, ev1 = 0, ev2 = 0;
    bool ok = false;
    Streams() {
        ok = cudaStreamCreateWithFlags(&s1, cudaStreamNonBlocking) == cudaSuccess &&
             cudaEventCreateWithFlags(&ev0, cudaEventDisableTiming) == cudaSuccess &&
             cudaEventCreateWithFlags(&ev1, cudaEventDisableTiming) == cudaSuccess &&
             cudaEventCreateWithFlags(&ev2, cudaEventDisableTiming) == cudaSuccess;
    }
};

// ---------------- launch ----------------
extern "C" void kernel_launch(void* const* d_in, const int* in_sizes, int n_in,
                              void* d_out, int out_size) {
    const float* x        = (const float*)d_in[0];
    const void*  ei       = d_in[1];
    const float* W        = (const float*)d_in[2];
    const float* att_src  = (const float*)d_in[3];
    const float* att_dst  = (const float*)d_in[4];
    const float* gat_bias = (const float*)d_in[5];
    const float* skip_W   = (const float*)d_in[6];
    const float* skip_b   = (const float*)d_in[7];
    const float* ln_g     = (const float*)d_in[8];
    const float* ln_b     = (const float*)d_in[9];
    float* out = (float*)d_out;

    int nblocks = (NN + 1023) / 1024;
    dim3 ggrid((NN + BM - 1) / BM, 2);
    int prep_blocks = 64 + (NN * 32 + 255) / 256;
    const int EHALF = EE / 2;
    int sc_blocks = (EHALF / 2 + 255) / 256;

    static Streams st;

    if (st.ok) {
        detect_k<<<1, 32>>>((const long long*)ei);
        cudaEventRecord(st.ev0, 0);
        cudaStreamWaitEvent(st.s1, st.ev0, 0);
        // side stream: CSR build
        init_k<<<(NN + 255) / 256, 256, 0, st.s1>>>();
        hist_k<<<(EE / 2 + 255) / 256, 256, 0, st.s1>>>(ei);
        scanA_k<<<nblocks, 1024, 0, st.s1>>>();
        scanB_k<<<1, 128, 0, st.s1>>>(nblocks);
        scanC_k<<<(NN + 255) / 256, 256, 0, st.s1>>>();
        cudaEventRecord(st.ev2, st.s1);
        scatter_k<<<sc_blocks, 256, 0, st.s1>>>(ei, 0, EHALF);
        cudaEventRecord(st.ev1, st.s1);
        // main stream: prep + GEMM
        prep_k<<<prep_blocks, 256>>>(W, skip_W, x);
        gemm_fp16_k<<<ggrid, 256>>>(att_src, att_dst);
        cudaStreamWaitEvent(0, st.ev2, 0);
        scatter_k<<<sc_blocks, 256>>>(ei, EHALF, EE);
        cudaStreamWaitEvent(0, st.ev1, 0);
        eagg_k<<<(NN * 32 + 255) / 256, 256>>>(gat_bias, skip_b, ln_g, ln_b, out);
    } else {
        detect_k<<<1, 32>>>((const long long*)ei);
        prep_k<<<prep_blocks, 256>>>(W, skip_W, x);
        init_k<<<(NN + 255) / 256, 256>>>();
        gemm_fp16_k<<<ggrid, 256>>>(att_src, att_dst);
        hist_k<<<(EE / 2 + 255) / 256, 256>>>(ei);
        scanA_k<<<nblocks, 1024>>>();
        scanB_k<<<1, 128>>>(nblocks);
        scanC_k<<<(NN + 255) / 256, 256>>>();
        scatter_k<<<(EE / 2 + 255) / 256, 256>>>(ei, 0, EE);
        eagg_k<<<(NN * 32 + 255) / 256, 256>>>(gat_bias, skip_b, ln_g, ln_b, out);
    }
}